// round 6
// baseline (speedup 1.0000x reference)
#include <cuda_runtime.h>
#include <cuda_bf16.h>

// ---------------------------------------------------------------------------
// GuidedAttentionL1Loss — one warp PER SEGMENT, barrier-free hot path.
//  K1 scan: prefix-scan lengths -> g_starts (+sentinel)
//  K2 main: blocks [0,NMISC): params L1 + NLL
//           blocks [NMISC,..): 8 warps/block, warp w owns segment
//             b = (blk-NMISC)*8+w.  pass1 float4 -> (Sy,Sxy,Sy2) via shuffles;
//             pass2 re-read (L2-hot) -> (Se,Sye,Se2); label==1 segments use
//             the analytic 19-element Gaussian support window.
//           last-done block finalizes loss.
// ---------------------------------------------------------------------------

#define MAX_B 4096
#define NMISC 148
#define ALPHA_HALF 5.0e-4
#define BETA_HALF 0.05
#define NEXP2 (-0.72134752044448f)   /* -1/(2 ln 2) */

__device__ double g_psum = 0.0;
__device__ double g_nll  = 0.0;
__device__ double g_attn = 0.0;
__device__ int    g_done = 0;
__device__ int    g_starts[MAX_B + 1];

__device__ __forceinline__ bool detect_i64(const void* lengths) {
    // lengths[0] >= 1 always; int64 LE -> high word of element 0 is 0.
    return ((const int*)lengths)[1] == 0;
}
__device__ __forceinline__ int load_int(const void* p, int i, bool is64) {
    return is64 ? (int)((const long long*)p)[i] : ((const int*)p)[i];
}
__device__ __forceinline__ float ex2f(float a) {
    float r;
    asm("ex2.approx.ftz.f32 %0, %1;" : "=f"(r) : "f"(a));
    return r;
}
__device__ __forceinline__ void warp_sum3(float& a, float& b, float& c) {
    const unsigned full = 0xffffffffu;
#pragma unroll
    for (int o = 16; o > 0; o >>= 1) {
        a += __shfl_xor_sync(full, a, o);
        b += __shfl_xor_sync(full, b, o);
        c += __shfl_xor_sync(full, c, o);
    }
}

// ---------------------------------------------------------------------------
// K1: exclusive prefix scan of lengths -> g_starts, sentinel g_starts[B]=T.
// ---------------------------------------------------------------------------
__global__ __launch_bounds__(1024) void scan_kernel(const void* lengths, int B, int T) {
    __shared__ int wsum[32];
    int t = threadIdx.x, lane = t & 31, w = t >> 5;
    bool is64 = detect_i64(lengths);

    int l[4];
    int base = t * 4;
#pragma unroll
    for (int j = 0; j < 4; j++)
        l[j] = (base + j < B) ? load_int(lengths, base + j, is64) : 0;
    int tot = l[0] + l[1] + l[2] + l[3];

    int inc = tot;
#pragma unroll
    for (int o = 1; o < 32; o <<= 1) {
        int v = __shfl_up_sync(0xffffffffu, inc, o);
        if (lane >= o) inc += v;
    }
    if (lane == 31) wsum[w] = inc;
    __syncthreads();
    if (w == 0) {
        int v = wsum[lane];
#pragma unroll
        for (int o = 1; o < 32; o <<= 1) {
            int u = __shfl_up_sync(0xffffffffu, v, o);
            if (lane >= o) v += u;
        }
        wsum[lane] = v;
    }
    __syncthreads();
    int warp_base = (w > 0) ? wsum[w - 1] : 0;
    int run = warp_base + inc - tot;      // exclusive prefix
    if (t == 0) g_starts[B] = T;
#pragma unroll
    for (int j = 0; j < 4; j++) {
        if (base + j < B) g_starts[base + j] = run;
        run += l[j];
    }
}

// ---------------------------------------------------------------------------
// K2: main.
// ---------------------------------------------------------------------------
__global__ __launch_bounds__(256) void main_kernel(
    const float* __restrict__ logits, const float* __restrict__ params,
    const float* __restrict__ attn,
    const void* __restrict__ labels, const void* __restrict__ lengths,
    int P, int B, float* __restrict__ out, int out_size)
{
    int t = threadIdx.x;
    int lane = t & 31, wid = t >> 5;
    bool is64 = detect_i64(lengths);

    if (blockIdx.x < NMISC) {
        // ----- misc: L1 over params + NLL over logits -----
        __shared__ float red[2][32];
        int gid = blockIdx.x * 256 + t;
        int stride = NMISC * 256;
        float a = 0.0f;
        const float4* p4 = (const float4*)params;
        int n4 = P >> 2;
        for (int i = gid; i < n4; i += stride) {
            float4 v = __ldg(p4 + i);
            a += fabsf(v.x) + fabsf(v.y) + fabsf(v.z) + fabsf(v.w);
        }
        float nl = 0.0f;
        for (int b = gid; b < B; b += stride) {
            float l0 = logits[2 * b];
            float l1 = logits[2 * b + 1];
            int lab = load_int(labels, b, is64);
            float m = fmaxf(l0, l1);
            float lse = m + logf(expf(l0 - m) + expf(l1 - m));
            nl -= (lab ? l1 : l0) - lse;
        }
#pragma unroll
        for (int o = 16; o > 0; o >>= 1) {
            a  += __shfl_down_sync(0xffffffffu, a, o);
            nl += __shfl_down_sync(0xffffffffu, nl, o);
        }
        if (lane == 0) { red[0][wid] = a; red[1][wid] = nl; }
        __syncthreads();
        if (wid == 0) {
            a  = (lane < 8) ? red[0][lane] : 0.0f;
            nl = (lane < 8) ? red[1][lane] : 0.0f;
#pragma unroll
            for (int o = 4; o > 0; o >>= 1) {
                a  += __shfl_down_sync(0xffffffffu, a, o);
                nl += __shfl_down_sync(0xffffffffu, nl, o);
            }
            if (lane == 0) {
                if (a != 0.0f)  atomicAdd(&g_psum, (double)a);
                if (nl != 0.0f) atomicAdd(&g_nll, (double)nl);
            }
        }
    } else {
        // ----- one warp per segment -----
        __shared__ float part[8];
        int b = (blockIdx.x - NMISC) * 8 + wid;
        float acc = 0.0f;

        if (b < B) {
            int s = g_starts[b];
            int len = g_starts[b + 1] - s;
            const float* yp = attn + s;
            float lenf = (float)len;
            float invl = 1.0f / lenf;

            // --- pass 1: Sy, S(i+1)y, Sy2 ---
            int head = (int)((4u - ((unsigned)s & 3u)) & 3u);
            if (head > len) head = len;
            int nb = (len - head) >> 2;           // quads
            int tstart = head + (nb << 2);

            float s1 = 0.f, s2 = 0.f, s3 = 0.f;   // s2 holds S(i+1)*y
            if (lane < head) {
                float y = __ldg(yp + lane);
                s1 = y; s2 = (float)(lane + 1) * y; s3 = y * y;
            }
            const float4* q4 = (const float4*)(yp + head);
#pragma unroll 4
            for (int i = lane; i < nb; i += 32) {
                float4 v = __ldg(q4 + i);
                float idx = (float)(head + (i << 2) + 1);  // exact <= 3072
                s1 += v.x + v.y + v.z + v.w;
                s2 = fmaf(idx,        v.x, s2);
                s2 = fmaf(idx + 1.0f, v.y, s2);
                s2 = fmaf(idx + 2.0f, v.z, s2);
                s2 = fmaf(idx + 3.0f, v.w, s2);
                s3 = fmaf(v.x, v.x, s3);
                s3 = fmaf(v.y, v.y, s3);
                s3 = fmaf(v.z, v.z, s3);
                s3 = fmaf(v.w, v.w, s3);
            }
            if (lane < len - tstart) {
                int i = tstart + lane;
                float y = __ldg(yp + i);
                s1 += y; s2 = fmaf((float)(i + 1), y, s2); s3 = fmaf(y, y, s3);
            }
            warp_sum3(s1, s2, s3);
            float c = s2 / s1;                 // mean * len  (index units)
            float mean = c * invl;

            int lab = load_int(labels, b, is64);
            float istd = lab ? lenf : lenf * 1e-3f;
            float epsp = 2.5066283e-6f / istd;  // 1e-6*sqrt(2pi)/istd

            // --- pass 2: Se, Sye, Se2 ---
            float s4 = 0.f, s5 = 0.f, s6 = 0.f;
            if (lab) {
                // z = (i+1) - c, spacing 1 -> support |z|<9: <=19 elems
                int i_lo = (int)ceilf(c - 9.0f) - 1;
                if (i_lo < 0) i_lo = 0;
                int i_hi = (int)floorf(c + 9.0f) - 1;
                if (i_hi > len - 1) i_hi = len - 1;
                if (lane <= i_hi - i_lo) {
                    int i = i_lo + lane;
                    float y = __ldg(yp + i);
                    float z = (float)(i + 1) - c;
                    float e = ex2f(NEXP2 * z * z);
                    s4 = e; s5 = y * e; s6 = e * e;
                }
            } else {
                float m2 = NEXP2 * istd * istd;
                if (lane < head) {
                    float y = __ldg(yp + lane);
                    float d = (float)(lane + 1) * invl - mean;
                    float e = ex2f(m2 * d * d);
                    s4 = e; s5 = y * e; s6 = e * e;
                }
#pragma unroll 4
                for (int i = lane; i < nb; i += 32) {
                    float4 v = __ldg(q4 + i);
                    float d = (float)(head + (i << 2) + 1) * invl - mean;
                    float e0 = ex2f(m2 * d * d); d += invl;
                    float e1 = ex2f(m2 * d * d); d += invl;
                    float e2 = ex2f(m2 * d * d); d += invl;
                    float e3 = ex2f(m2 * d * d);
                    s4 += e0 + e1 + e2 + e3;
                    s5 = fmaf(v.x, e0, s5); s5 = fmaf(v.y, e1, s5);
                    s5 = fmaf(v.z, e2, s5); s5 = fmaf(v.w, e3, s5);
                    s6 = fmaf(e0, e0, s6); s6 = fmaf(e1, e1, s6);
                    s6 = fmaf(e2, e2, s6); s6 = fmaf(e3, e3, s6);
                }
                if (lane < len - tstart) {
                    int i = tstart + lane;
                    float y = __ldg(yp + i);
                    float d = (float)(i + 1) * invl - mean;
                    float e = ex2f(m2 * d * d);
                    s4 += e; s5 = fmaf(y, e, s5); s6 = fmaf(e, e, s6);
                }
            }
            warp_sum3(s4, s5, s6);

            float rs = 1.0f / (s4 + epsp);
            float D2 = s3 - 2.0f * rs * s5 + rs * rs * s6;
            acc = D2 * invl;
        }

        if (lane == 0) part[wid] = acc;
        __syncthreads();
        if (t == 0) {
            float sum = 0.0f;
#pragma unroll
            for (int j = 0; j < 8; j++) sum += part[j];
            if (sum != 0.0f) atomicAdd(&g_attn, (double)sum);
        }
    }

    // ----- last-done block finalizes + resets -----
    __threadfence();
    __syncthreads();
    if (t == 0) {
        int prev = atomicAdd(&g_done, 1);
        if (prev == (int)gridDim.x - 1) {
            double invB = 1.0 / (double)B;
            double nll = g_nll * invB;
            double loss = nll + ALPHA_HALF * g_psum + BETA_HALF * (g_attn * invB);
            out[0] = (float)loss;
            if (out_size > 1) out[1] = (float)nll;
            g_psum = 0.0; g_nll = 0.0; g_attn = 0.0;
            __threadfence();
            g_done = 0;
        }
    }
}

extern "C" void kernel_launch(void* const* d_in, const int* in_sizes, int n_in,
                              void* d_out, int out_size) {
    const float* logits  = (const float*)d_in[0];
    const float* params  = (const float*)d_in[1];
    const float* attn    = (const float*)d_in[2];
    const void*  labels  = d_in[3];
    const void*  lengths = d_in[4];
    // d_in[5] = seg_ids: unused

    int P = in_sizes[1];
    int B = in_sizes[3];
    int T = in_sizes[2];

    int nsegblk = (B + 7) >> 3;       // 8 warps/block, 1 segment per warp

    scan_kernel<<<1, 1024>>>(lengths, B, T);
    main_kernel<<<NMISC + nsegblk, 256>>>(logits, params, attn, labels, lengths,
                                          P, B, (float*)d_out, out_size);
}

// round 7
// speedup vs baseline: 1.0399x; 1.0399x over previous
#include <cuda_runtime.h>
#include <cuda_bf16.h>

// ---------------------------------------------------------------------------
// GuidedAttentionL1Loss — one warp per segment; Gaussian recurrence (no MUFU
// in the hot loop).
//  K1 scan: prefix-scan lengths -> g_starts (+sentinel)
//  K2 main: blocks [0,NMISC): params L1 + NLL
//           blocks [NMISC,..): warp w owns segment b.
//             pass1 float4 -> (Sy, S(i+1)y, Sy2) via shuffles
//             pass2 label==1: analytic 19-elem window (<=19 exps)
//                   label==0: e=exp(-z^2/2) by multiplicative recurrence:
//                     z step/elem = 1e-3 exactly; per-lane quad stride
//                     s=0.128 => E *= R, R *= C with C,c_j constants.
//           last-done block finalizes loss.
// ---------------------------------------------------------------------------

#define MAX_B 4096
#define NMISC 148
#define ALPHA_HALF 5.0e-4
#define BETA_HALF 0.05
#define NEXP2 (-0.72134752044448f)   /* -1/(2 ln 2): exp(-u/2)=ex2(NEXP2*u) */
#define DLT   1.0e-3f                /* z step per element (label==0) */
#define SSTP  0.128f                 /* z step per lane-quad (128 elems) */
#define CC    0.983749488f           /* exp(-SSTP^2) */
#define C1    0.999872008f           /* exp(-SSTP*DLT)   */
#define C2    0.999744033f           /* exp(-2*SSTP*DLT) */
#define C3    0.999616074f           /* exp(-3*SSTP*DLT) */

__device__ double g_psum = 0.0;
__device__ double g_nll  = 0.0;
__device__ double g_attn = 0.0;
__device__ int    g_done = 0;
__device__ int    g_starts[MAX_B + 1];

__device__ __forceinline__ bool detect_i64(const void* lengths) {
    // lengths[0] >= 1 always; int64 LE -> high word of element 0 is 0.
    return ((const int*)lengths)[1] == 0;
}
__device__ __forceinline__ int load_int(const void* p, int i, bool is64) {
    return is64 ? (int)((const long long*)p)[i] : ((const int*)p)[i];
}
__device__ __forceinline__ float ex2f(float a) {
    float r;
    asm("ex2.approx.ftz.f32 %0, %1;" : "=f"(r) : "f"(a));
    return r;
}
__device__ __forceinline__ void warp_sum3(float& a, float& b, float& c) {
    const unsigned full = 0xffffffffu;
#pragma unroll
    for (int o = 16; o > 0; o >>= 1) {
        a += __shfl_xor_sync(full, a, o);
        b += __shfl_xor_sync(full, b, o);
        c += __shfl_xor_sync(full, c, o);
    }
}

// ---------------------------------------------------------------------------
// K1: exclusive prefix scan of lengths -> g_starts, sentinel g_starts[B]=T.
// ---------------------------------------------------------------------------
__global__ __launch_bounds__(1024) void scan_kernel(const void* lengths, int B, int T) {
    __shared__ int wsum[32];
    int t = threadIdx.x, lane = t & 31, w = t >> 5;
    bool is64 = detect_i64(lengths);

    int l[4];
    int base = t * 4;
#pragma unroll
    for (int j = 0; j < 4; j++)
        l[j] = (base + j < B) ? load_int(lengths, base + j, is64) : 0;
    int tot = l[0] + l[1] + l[2] + l[3];

    int inc = tot;
#pragma unroll
    for (int o = 1; o < 32; o <<= 1) {
        int v = __shfl_up_sync(0xffffffffu, inc, o);
        if (lane >= o) inc += v;
    }
    if (lane == 31) wsum[w] = inc;
    __syncthreads();
    if (w == 0) {
        int v = wsum[lane];
#pragma unroll
        for (int o = 1; o < 32; o <<= 1) {
            int u = __shfl_up_sync(0xffffffffu, v, o);
            if (lane >= o) v += u;
        }
        wsum[lane] = v;
    }
    __syncthreads();
    int warp_base = (w > 0) ? wsum[w - 1] : 0;
    int run = warp_base + inc - tot;
    if (t == 0) g_starts[B] = T;
#pragma unroll
    for (int j = 0; j < 4; j++) {
        if (base + j < B) g_starts[base + j] = run;
        run += l[j];
    }
}

// ---------------------------------------------------------------------------
// K2: main.
// ---------------------------------------------------------------------------
__global__ __launch_bounds__(256) void main_kernel(
    const float* __restrict__ logits, const float* __restrict__ params,
    const float* __restrict__ attn,
    const void* __restrict__ labels, const void* __restrict__ lengths,
    int P, int B, float* __restrict__ out, int out_size)
{
    int t = threadIdx.x;
    int lane = t & 31, wid = t >> 5;
    bool is64 = detect_i64(lengths);

    if (blockIdx.x < NMISC) {
        // ----- misc: L1 over params + NLL over logits -----
        __shared__ float red[2][32];
        int gid = blockIdx.x * 256 + t;
        int stride = NMISC * 256;
        float a = 0.0f;
        const float4* p4 = (const float4*)params;
        int n4 = P >> 2;
        for (int i = gid; i < n4; i += stride) {
            float4 v = __ldg(p4 + i);
            a += fabsf(v.x) + fabsf(v.y) + fabsf(v.z) + fabsf(v.w);
        }
        float nl = 0.0f;
        for (int b = gid; b < B; b += stride) {
            float l0 = logits[2 * b];
            float l1 = logits[2 * b + 1];
            int lab = load_int(labels, b, is64);
            float m = fmaxf(l0, l1);
            float lse = m + logf(expf(l0 - m) + expf(l1 - m));
            nl -= (lab ? l1 : l0) - lse;
        }
#pragma unroll
        for (int o = 16; o > 0; o >>= 1) {
            a  += __shfl_down_sync(0xffffffffu, a, o);
            nl += __shfl_down_sync(0xffffffffu, nl, o);
        }
        if (lane == 0) { red[0][wid] = a; red[1][wid] = nl; }
        __syncthreads();
        if (wid == 0) {
            a  = (lane < 8) ? red[0][lane] : 0.0f;
            nl = (lane < 8) ? red[1][lane] : 0.0f;
#pragma unroll
            for (int o = 4; o > 0; o >>= 1) {
                a  += __shfl_down_sync(0xffffffffu, a, o);
                nl += __shfl_down_sync(0xffffffffu, nl, o);
            }
            if (lane == 0) {
                if (a != 0.0f)  atomicAdd(&g_psum, (double)a);
                if (nl != 0.0f) atomicAdd(&g_nll, (double)nl);
            }
        }
    } else {
        // ----- one warp per segment -----
        __shared__ float part[8];
        int b = (blockIdx.x - NMISC) * 8 + wid;
        float acc = 0.0f;

        if (b < B) {
            int s = g_starts[b];
            int len = g_starts[b + 1] - s;
            const float* yp = attn + s;
            float lenf = (float)len;
            float invl = 1.0f / lenf;

            int head = (int)((4u - ((unsigned)s & 3u)) & 3u);
            if (head > len) head = len;
            int nb = (len - head) >> 2;           // quads
            int tstart = head + (nb << 2);

            // --- pass 1: Sy, S(i+1)y, Sy2 ---
            float s1 = 0.f, s2 = 0.f, s3 = 0.f;
            if (lane < head) {
                float y = __ldg(yp + lane);
                s1 = y; s2 = (float)(lane + 1) * y; s3 = y * y;
            }
            const float4* q4 = (const float4*)(yp + head);
#pragma unroll 8
            for (int i = lane; i < nb; i += 32) {
                float4 v = __ldg(q4 + i);
                float idx = (float)(head + (i << 2) + 1);
                s1 += v.x + v.y + v.z + v.w;
                s2 = fmaf(idx,        v.x, s2);
                s2 = fmaf(idx + 1.0f, v.y, s2);
                s2 = fmaf(idx + 2.0f, v.z, s2);
                s2 = fmaf(idx + 3.0f, v.w, s2);
                s3 = fmaf(v.x, v.x, s3);
                s3 = fmaf(v.y, v.y, s3);
                s3 = fmaf(v.z, v.z, s3);
                s3 = fmaf(v.w, v.w, s3);
            }
            if (lane < len - tstart) {
                int i = tstart + lane;
                float y = __ldg(yp + i);
                s1 += y; s2 = fmaf((float)(i + 1), y, s2); s3 = fmaf(y, y, s3);
            }
            warp_sum3(s1, s2, s3);
            float c = s2 / s1;                 // mean in index units (mean*len)

            int lab = load_int(labels, b, is64);
            float istd = lab ? lenf : lenf * 1e-3f;
            float epsp = 2.5066283e-6f / istd;

            // --- pass 2: Se, Sye, Se2 ---
            float s4 = 0.f, s5 = 0.f, s6 = 0.f;
            if (lab) {
                // z = (i+1) - c, spacing 1 -> support |z|<9: <=19 elems
                int i_lo = (int)ceilf(c - 9.0f) - 1;
                if (i_lo < 0) i_lo = 0;
                int i_hi = (int)floorf(c + 9.0f) - 1;
                if (i_hi > len - 1) i_hi = len - 1;
                if (lane <= i_hi - i_lo) {
                    int i = i_lo + lane;
                    float y = __ldg(yp + i);
                    float z = (float)(i + 1) - c;
                    float e = ex2f(NEXP2 * z * z);
                    s4 = e; s5 = y * e; s6 = e * e;
                }
            } else {
                // z = ((i+1) - c) * 1e-3; recurrence per lane, 4 streams/quad
                if (lane < head) {
                    float y = __ldg(yp + lane);
                    float z = ((float)(lane + 1) - c) * DLT;
                    float e = ex2f(NEXP2 * z * z);
                    s4 = e; s5 = y * e; s6 = e * e;
                }
                // init at lane's first quad: elements head+4*lane+{0..3}
                float z0 = ((float)(head + 4 * lane + 1) - c) * DLT;
                float E0 = ex2f(NEXP2 * z0 * z0);
                float z1 = z0 + DLT;
                float E1 = ex2f(NEXP2 * z1 * z1);
                float z2 = z1 + DLT;
                float E2 = ex2f(NEXP2 * z2 * z2);
                float z3 = z2 + DLT;
                float E3 = ex2f(NEXP2 * z3 * z3);
                // ratio for stride s=0.128: exp(-(2*s*z0+s^2)/2)
                float R = ex2f(NEXP2 * fmaf(2.0f * SSTP, z0, SSTP * SSTP));
#pragma unroll 4
                for (int i = lane; i < nb; i += 32) {
                    float4 v = __ldg(q4 + i);
                    s4 += E0 + E1 + E2 + E3;
                    s5 = fmaf(v.x, E0, s5); s5 = fmaf(v.y, E1, s5);
                    s5 = fmaf(v.z, E2, s5); s5 = fmaf(v.w, E3, s5);
                    s6 = fmaf(E0, E0, s6); s6 = fmaf(E1, E1, s6);
                    s6 = fmaf(E2, E2, s6); s6 = fmaf(E3, E3, s6);
                    E0 *= R;
                    E1 *= R * C1;
                    E2 *= R * C2;
                    E3 *= R * C3;
                    R *= CC;
                }
                if (lane < len - tstart) {
                    int i = tstart + lane;
                    float y = __ldg(yp + i);
                    float z = ((float)(i + 1) - c) * DLT;
                    float e = ex2f(NEXP2 * z * z);
                    s4 += e; s5 = fmaf(y, e, s5); s6 = fmaf(e, e, s6);
                }
            }
            warp_sum3(s4, s5, s6);

            float rs = 1.0f / (s4 + epsp);
            float D2 = s3 - 2.0f * rs * s5 + rs * rs * s6;
            acc = D2 * invl;
        }

        if (lane == 0) part[wid] = acc;
        __syncthreads();
        if (t == 0) {
            float sum = 0.0f;
#pragma unroll
            for (int j = 0; j < 8; j++) sum += part[j];
            if (sum != 0.0f) atomicAdd(&g_attn, (double)sum);
        }
    }

    // ----- last-done block finalizes + resets -----
    __threadfence();
    __syncthreads();
    if (t == 0) {
        int prev = atomicAdd(&g_done, 1);
        if (prev == (int)gridDim.x - 1) {
            double invB = 1.0 / (double)B;
            double nll = g_nll * invB;
            double loss = nll + ALPHA_HALF * g_psum + BETA_HALF * (g_attn * invB);
            out[0] = (float)loss;
            if (out_size > 1) out[1] = (float)nll;
            g_psum = 0.0; g_nll = 0.0; g_attn = 0.0;
            __threadfence();
            g_done = 0;
        }
    }
}

extern "C" void kernel_launch(void* const* d_in, const int* in_sizes, int n_in,
                              void* d_out, int out_size) {
    const float* logits  = (const float*)d_in[0];
    const float* params  = (const float*)d_in[1];
    const float* attn    = (const float*)d_in[2];
    const void*  labels  = d_in[3];
    const void*  lengths = d_in[4];
    // d_in[5] = seg_ids: unused

    int P = in_sizes[1];
    int B = in_sizes[3];
    int T = in_sizes[2];

    int nsegblk = (B + 7) >> 3;

    scan_kernel<<<1, 1024>>>(lengths, B, T);
    main_kernel<<<NMISC + nsegblk, 256>>>(logits, params, attn, labels, lengths,
                                          P, B, (float*)d_out, out_size);
}